// round 1
// baseline (speedup 1.0000x reference)
#include <cuda_runtime.h>

#define V 6
#define U 4
#define NSTATE (V*U)   // 24
#define STEPS 63       // 64th step's output is discarded by the reference

__device__ float g_vels[8];

__device__ __forceinline__ float fast_sigmoid(float x) {
    // 1 / (1 + e^-x); saturates correctly at +-inf
    return __fdividef(1.0f, 1.0f + __expf(-x));
}

__device__ __forceinline__ float fast_tanh(float x) {
    // tanh(x) = 1 - 2/(e^{2x}+1); correct limits at +-inf
    return 1.0f - __fdividef(2.0f, __expf(2.0f * x) + 1.0f);
}

__global__ void recurrence_kernel(
    const float* __restrict__ vel,
    const float* __restrict__ Wix, const float* __restrict__ Wih, const float* __restrict__ bi,
    const float* __restrict__ Wfx, const float* __restrict__ Wfh, const float* __restrict__ bf,
    const float* __restrict__ Wox, const float* __restrict__ Woh, const float* __restrict__ bo,
    const float* __restrict__ Wgx, const float* __restrict__ Wgh, const float* __restrict__ bg,
    const float* __restrict__ linear, const float* __restrict__ bl,
    const float* __restrict__ h0, const float* __restrict__ c0)
{
    const unsigned FULL = 0xFFFFFFFFu;
    int lane = threadIdx.x & 31;
    int t = (lane < NSTATE) ? lane : 0;   // idle lanes shadow lane 0 (results ignored)
    int j = t >> 2;                        // veldim index
    int u = t & 3;                         // unit index
    int base = j << 2;                     // first lane of this group of 4

    // Per-element weights into registers
    float wix = Wix[t], wfx = Wfx[t], wox = Wox[t], wgx = Wgx[t];
    float bii = bi[t],  bff = bf[t],  boo = bo[t],  bgg = bg[t];
    float wih[4], wfh[4], woh[4], wgh[4];
#pragma unroll
    for (int k = 0; k < 4; ++k) {
        wih[k] = Wih[t * 4 + k];
        wfh[k] = Wfh[t * 4 + k];
        woh[k] = Woh[t * 4 + k];
        wgh[k] = Wgh[t * 4 + k];
    }
    float lin = linear[t];
    float blj = bl[j];

    float h = h0[t];
    float c = c0[t];
    float x = vel[j];        // step 1 input: vel broadcast along U
    float vacc = 0.0f;

    for (int s = 0; s < STEPS; ++s) {
        // Gather this group's 4 h values (needed by all 4 gate dots)
        float ha = __shfl_sync(FULL, h, base + 0);
        float hb = __shfl_sync(FULL, h, base + 1);
        float hc = __shfl_sync(FULL, h, base + 2);
        float hd = __shfl_sync(FULL, h, base + 3);

        float pi = fmaf(wix, x, bii);
        float pf = fmaf(wfx, x, bff);
        float po = fmaf(wox, x, boo);
        float pg = fmaf(wgx, x, bgg);

        pi = fmaf(wih[0], ha, pi); pi = fmaf(wih[1], hb, pi);
        pi = fmaf(wih[2], hc, pi); pi = fmaf(wih[3], hd, pi);
        pf = fmaf(wfh[0], ha, pf); pf = fmaf(wfh[1], hb, pf);
        pf = fmaf(wfh[2], hc, pf); pf = fmaf(wfh[3], hd, pf);
        po = fmaf(woh[0], ha, po); po = fmaf(woh[1], hb, po);
        po = fmaf(woh[2], hc, po); po = fmaf(woh[3], hd, po);
        pg = fmaf(wgh[0], ha, pg); pg = fmaf(wgh[1], hb, pg);
        pg = fmaf(wgh[2], hc, pg); pg = fmaf(wgh[3], hd, pg);

        float it = fast_sigmoid(pi);
        float ft = fast_sigmoid(pf);
        float ot = fast_sigmoid(po);
        float gt = fast_sigmoid(pg);   // reference uses sigmoid here too

        c = fmaf(ft, c, it * gt);
        h = ot * fast_sigmoid(c);      // reference uses sigmoid (not tanh)

        // out[j] = tanh( sum_u linear[j,u]*h[j,u] + bl[j] )
        float ssum = lin * h;
        ssum += __shfl_xor_sync(FULL, ssum, 1);
        ssum += __shfl_xor_sync(FULL, ssum, 2);
        x = fast_tanh(ssum + blj);

        // vels = 2*out1 + sum_{t=2..63} out_t  (reference scan double-counts out1)
        vacc += (s == 0) ? 2.0f * x : x;
    }

    if (lane < NSTATE && u == 0) g_vels[j] = vacc;
}

__global__ void __launch_bounds__(256) apply_kernel(
    const float4* __restrict__ lsx,
    const float4* __restrict__ lsy,
    float4* __restrict__ out,
    int npairs)
{
    int t = blockIdx.x * blockDim.x + threadIdx.x;
    if (t >= npairs) return;

    float v0 = g_vels[0], v1 = g_vels[1], v2 = g_vels[2];
    float v3 = g_vels[3], v4 = g_vels[4], v5 = g_vels[5];

    const float4* px = lsx + 3 * (size_t)t;
    const float4* py = lsy + 3 * (size_t)t;
    float4 a = px[0], b = px[1], cc = px[2];
    float4 d = py[0], e = py[1], f = py[2];

    // pixel 2t   : elements a.x..a.w, b.x, b.y
    // pixel 2t+1 : elements b.z, b.w, cc.x..cc.w
    float fx0 = fmaf(a.x, v0, fmaf(a.y, v1, fmaf(a.z, v2,
                fmaf(a.w, v3, fmaf(b.x, v4, b.y * v5)))));
    float fx1 = fmaf(b.z, v0, fmaf(b.w, v1, fmaf(cc.x, v2,
                fmaf(cc.y, v3, fmaf(cc.z, v4, cc.w * v5)))));
    float fy0 = fmaf(d.x, v0, fmaf(d.y, v1, fmaf(d.z, v2,
                fmaf(d.w, v3, fmaf(e.x, v4, e.y * v5)))));
    float fy1 = fmaf(e.z, v0, fmaf(e.w, v1, fmaf(f.x, v2,
                fmaf(f.y, v3, fmaf(f.z, v4, f.w * v5)))));

    out[t] = make_float4(fx0, fy0, fx1, fy1);
}

extern "C" void kernel_launch(void* const* d_in, const int* in_sizes, int n_in,
                              void* d_out, int out_size)
{
    const float* vel = (const float*)d_in[0];
    const float* Lsx = (const float*)d_in[1];
    const float* Lsy = (const float*)d_in[2];
    const float* Wix = (const float*)d_in[3];
    const float* Wih = (const float*)d_in[4];
    const float* bi  = (const float*)d_in[5];
    const float* Wfx = (const float*)d_in[6];
    const float* Wfh = (const float*)d_in[7];
    const float* bf  = (const float*)d_in[8];
    const float* Wox = (const float*)d_in[9];
    const float* Woh = (const float*)d_in[10];
    const float* bo  = (const float*)d_in[11];
    const float* Wgx = (const float*)d_in[12];
    const float* Wgh = (const float*)d_in[13];
    const float* bg  = (const float*)d_in[14];
    const float* linear = (const float*)d_in[15];
    const float* bl  = (const float*)d_in[16];
    const float* h0  = (const float*)d_in[17];
    const float* c0  = (const float*)d_in[18];

    int N = in_sizes[1] / V;       // pixels
    int npairs = N / 2;            // N is even (1920*1080)

    recurrence_kernel<<<1, 32>>>(vel, Wix, Wih, bi, Wfx, Wfh, bf,
                                 Wox, Woh, bo, Wgx, Wgh, bg,
                                 linear, bl, h0, c0);

    apply_kernel<<<(npairs + 255) / 256, 256>>>(
        (const float4*)Lsx, (const float4*)Lsy, (float4*)d_out, npairs);
}